// round 15
// baseline (speedup 1.0000x reference)
#include <cuda_runtime.h>
#include <cuda_bf16.h>
#include <cuda_fp16.h>
#include <cuda_fp8.h>
#include <math.h>

#define NN    20000     // N_U == N_I
#define NNP   20096     // padded to multiple of 128
#define DIM   256
#define NNZ_  600000
#define NE_   300000
#define B_    8192
#define FSC   512.0f    // fp8 storage scale
#define FSCI  (1.0f/512.0f)

// ---------------- persistent device scratch (no allocations allowed) -------
__device__ float d_alg[NN], d_arg_[NN], d_ald[NN], d_ard[NN];
__device__ float d_s[2*B_];
__device__ double d_lr_acc, d_reg_acc;
// CSR structures (rebuilt every launch)
__device__ int   d_ctl[8*(NN+1)];            // cnt0,cnt1,cur0,cur1,cnt2,cnt3,cur2,cur3
__device__ int   d_off[4*(NN+1)];            // off0, off1, off2, off3
__device__ int   d_payg[NE_], d_payd[NE_];   // attention payload: src node
__device__ int2  d_pe1[NNZ_], d_pe2[NNZ_];   // spmm payload: {col, w-bits}
// fp8 scratch (values stored scaled by FSC)
__device__ unsigned char d_hg8[NNP*DIM], d_hd8[NNP*DIM];     // h = X @ att_W
__device__ unsigned char d_Eg0b8[NN*DIM], d_Ed0b8[NN*DIM];   // post-attention emb
// bf16 scratch
__device__ __nv_bfloat16 d_Eg0h[NNP*DIM], d_Ed0h[NNP*DIM];   // padded rows stay 0
__device__ __nv_bfloat16 d_attWt[DIM*DIM];                    // [N,K] transposed
__device__ __nv_bfloat16 d_W1t[DIM*2*DIM], d_W2t[DIM*DIM];    // transposed
__device__ __nv_bfloat16 d_catb[2*B_*2*DIM], d_h1b[2*B_*DIM];

struct ScanArgs { const int* cnt[4]; int* off[4]; };
struct P16 { const float* p[16]; int n[16]; };

__device__ __forceinline__ double softplusd(double x){
    return fmax(x, 0.0) + log1p(exp(-fabs(x)));
}

__device__ __forceinline__ uint4 pack8(const float* f){
    uint4 v;
    __nv_bfloat162* p = (__nv_bfloat162*)&v;
    #pragma unroll
    for (int i = 0; i < 4; i++)
        p[i] = __floats2bfloat162_rn(f[2*i], f[2*i+1]);
    return v;
}

// 8 e4m3 bytes (uint2) -> 8 floats (still in FSC-scaled units)
__device__ __forceinline__ void unpack8_fp8(uint2 v, float* f){
    __nv_fp8x2_storage_t* p = (__nv_fp8x2_storage_t*)&v;
    #pragma unroll
    for (int i = 0; i < 4; i++){
        __half2_raw hr = __nv_cvt_fp8x2_to_halfraw2(p[i], __NV_E4M3);
        float2 t = __half22float2(*(__half2*)&hr);
        f[2*i] = t.x; f[2*i+1] = t.y;
    }
}

// 8 floats (FSC-scaled) -> 8 e4m3 bytes
__device__ __forceinline__ uint2 pack8_fp8(const float* f){
    uint2 v;
    __nv_fp8x2_storage_t* p = (__nv_fp8x2_storage_t*)&v;
    #pragma unroll
    for (int i = 0; i < 4; i++)
        p[i] = __nv_cvt_float2_to_fp8x2(make_float2(f[2*i], f[2*i+1]),
                                        __NV_SATFINITE, __NV_E4M3);
    return v;
}

__device__ __forceinline__ void cpa16(void* smem, const void* gmem){
    unsigned saddr = (unsigned)__cvta_generic_to_shared(smem);
    asm volatile("cp.async.cg.shared.global [%0], [%1], 16;\n"
                 :: "r"(saddr), "l"(gmem));
}

// ---------------- f32 -> bf16, both embedding tables, vectorized ----------
__global__ void conv2_k(const float* __restrict__ a, const float* __restrict__ b,
                        __nv_bfloat16* __restrict__ oa, __nv_bfloat16* __restrict__ ob,
                        int nvec){
    int i = blockIdx.x*blockDim.x + threadIdx.x;
    if (i >= 2*nvec) return;
    const float* src; __nv_bfloat16* dst; int j;
    if (i < nvec){ src = a; dst = oa; j = i; }
    else         { src = b; dst = ob; j = i - nvec; }
    float4 v = ((const float4*)src)[j];
    __nv_bfloat162 lo = __floats2bfloat162_rn(v.x, v.y);
    __nv_bfloat162 hi = __floats2bfloat162_rn(v.z, v.w);
    uint2 pk; pk.x = *(unsigned*)&lo; pk.y = *(unsigned*)&hi;
    ((uint2*)dst)[j] = pk;
}

// ---------------- all three weight transposes, one launch ------------------
__global__ void convT3_k(const float* __restrict__ attW, const float* __restrict__ W1,
                         const float* __restrict__ W2,
                         __nv_bfloat16* __restrict__ attWt, __nv_bfloat16* __restrict__ W1t,
                         __nv_bfloat16* __restrict__ W2t){
    int z = blockIdx.z;
    const float* in; __nv_bfloat16* out; int K, N;
    if (z == 0){ in = attW; out = attWt; K = DIM;   N = DIM; }
    else if (z == 1){ in = W1; out = W1t; K = 2*DIM; N = DIM; }
    else { in = W2; out = W2t; K = DIM; N = DIM; }
    int i = blockIdx.x*blockDim.x + threadIdx.x;
    if (i >= K*N) return;
    int k = i / N, n = i % N;
    out[(size_t)n*K + k] = __float2bfloat16(in[i]);
}

// ---------------- all four histograms, one launch --------------------------
__global__ void hist4_k(const int* __restrict__ k0, const int* __restrict__ k1,
                        const int* __restrict__ k2, const int* __restrict__ k3,
                        int* __restrict__ c0, int* __restrict__ c1,
                        int* __restrict__ c2, int* __restrict__ c3){
    int i = blockIdx.x*blockDim.x + threadIdx.x;
    if (i < NE_)                  atomicAdd(&c0[k0[i]], 1);
    else if (i < 2*NE_)           atomicAdd(&c1[k1[i - NE_]], 1);
    else if (i < 2*NE_ + NNZ_)    atomicAdd(&c2[k2[i - 2*NE_]], 1);
    else if (i < 2*NE_ + 2*NNZ_)  atomicAdd(&c3[k3[i - 2*NE_ - NNZ_]], 1);
}

// one block per array; 256 threads; exclusive scan of n counts -> off[0..n]
__global__ void scan4_k(ScanArgs a, int n){
    const int* cnt = a.cnt[blockIdx.x];
    int* off = a.off[blockIdx.x];
    __shared__ int part[256];
    int tid = threadIdx.x;
    int per = (n + 255) / 256;
    int st = tid*per, en = st + per; if (en > n) en = n;
    int s = 0;
    for (int i = st; i < en; i++) s += cnt[i];
    part[tid] = s;
    __syncthreads();
    for (int o = 1; o < 256; o <<= 1){
        int v = (tid >= o) ? part[tid - o] : 0;
        __syncthreads();
        part[tid] += v;
        __syncthreads();
    }
    int base = tid ? part[tid - 1] : 0;
    for (int i = st; i < en; i++){ off[i] = base; base += cnt[i]; }
    if (tid == 255) off[n] = part[255];
}

// ---------------- attention CSR build, both graphs (z-batched) -------------
__global__ void build_att2_k(const int* __restrict__ ge, const int* __restrict__ de,
                             int* __restrict__ cur0, int* __restrict__ cur1,
                             const int* __restrict__ off0, const int* __restrict__ off1,
                             int* __restrict__ payg, int* __restrict__ payd){
    int i = blockIdx.x*blockDim.x + threadIdx.x;
    if (i >= NE_) return;
    const int* src; const int* tgt; int* cur; const int* off; int* pay;
    if (blockIdx.z == 0){ src = ge; tgt = ge + NE_; cur = cur0; off = off0; pay = payg; }
    else                { src = de; tgt = de + NE_; cur = cur1; off = off1; pay = payd; }
    int t = tgt[i];
    int p = atomicAdd(&cur[t], 1);
    pay[off[t] + p] = src[i];
}

// ---------------- adjacency CSR build + dropout weights, packed int2 -------
__global__ void build_adj2_k(const int* __restrict__ arows, const int* __restrict__ acols,
                             const float* __restrict__ vals,
                             const unsigned* __restrict__ m1, const unsigned* __restrict__ m2,
                             int* __restrict__ cur2, int* __restrict__ cur3,
                             const int* __restrict__ off2, const int* __restrict__ off3,
                             int2* __restrict__ pe1, int2* __restrict__ pe2){
    int i = blockIdx.x*blockDim.x + threadIdx.x;
    if (i >= NNZ_) return;
    const int* keys; const int* other; const unsigned* mask;
    int* cur; const int* off; int2* pe;
    if (blockIdx.z == 0){ keys = arows; other = acols; mask = m1; cur = cur2; off = off2; pe = pe1; }
    else                { keys = acols; other = arows; mask = m2; cur = cur3; off = off3; pe = pe2; }
    int k = keys[i];
    int p = atomicAdd(&cur[k], 1);
    float w = mask[i] ? vals[i] * (1.0f/0.9f) : 0.f;
    pe[off[k] + p] = make_int2(other[i], __float_as_int(w));
}

// ---------------- bf16 tensor-core GEMM, cp.async double-buffered ----------
// C[M,N] = A[M,K] @ B[K,N]; A bf16 row-major, Bt = B^T bf16 [N,K].
// Outputs: fp8 store scaled by FSC (C8*), or bf16 store (Cb*).
// Optional: attention rowdot atomics from fp8-rounded values (atta/al/ar),
// final-score atomics (W3/sv). blockIdx.z selects batch.
__global__ void hgemm_k(int M, int N, int K,
    const __nv_bfloat16* __restrict__ A0, const __nv_bfloat16* __restrict__ A1,
    const __nv_bfloat16* __restrict__ Bt,
    unsigned char* __restrict__ C80, unsigned char* __restrict__ C81,
    __nv_bfloat16* __restrict__ Cb0, __nv_bfloat16* __restrict__ Cb1,
    const float* __restrict__ bias, int relu,
    const float* __restrict__ atta,
    float* __restrict__ al0, float* __restrict__ ar0,
    float* __restrict__ al1, float* __restrict__ ar1, int rowlim,
    const float* __restrict__ W3, float* __restrict__ sv){
    const __nv_bfloat16* A = blockIdx.z ? A1 : A0;
    unsigned char* C8 = blockIdx.z ? C81 : C80;
    __nv_bfloat16* Cb = blockIdx.z ? Cb1 : Cb0;
    float* al = blockIdx.z ? al1 : al0;
    float* ar = blockIdx.z ? ar1 : ar0;
    __shared__ __nv_bfloat16 As[2][128][40];
    __shared__ __nv_bfloat16 Bs[2][128][40];
    int tid = threadIdx.x;
    int wid = tid >> 5, lane = tid & 31;
    int g = lane >> 2, tg = lane & 3;
    int wm = (wid & 1) * 64, wn = (wid >> 1) * 32;
    int row0 = blockIdx.y * 128, col0 = blockIdx.x * 128;
    int lr_ = tid >> 2, lc = (tid & 3) * 8;   // load coords: 4 threads per row
    float acc[4][4][4] = {};
    int nk = K >> 5;
    // prologue: stage 0
    {
        cpa16(&As[0][lr_][lc],      A  + (size_t)(row0 + lr_)*K + lc);
        cpa16(&As[0][lr_ + 64][lc], A  + (size_t)(row0 + lr_ + 64)*K + lc);
        cpa16(&Bs[0][lr_][lc],      Bt + (size_t)(col0 + lr_)*K + lc);
        cpa16(&Bs[0][lr_ + 64][lc], Bt + (size_t)(col0 + lr_ + 64)*K + lc);
        asm volatile("cp.async.commit_group;");
    }
    for (int ks0 = 0; ks0 < nk; ks0++){
        int cur = ks0 & 1;
        if (ks0 + 1 < nk){
            int nxt = cur ^ 1;
            int k0 = (ks0 + 1) << 5;
            cpa16(&As[nxt][lr_][lc],      A  + (size_t)(row0 + lr_)*K + k0 + lc);
            cpa16(&As[nxt][lr_ + 64][lc], A  + (size_t)(row0 + lr_ + 64)*K + k0 + lc);
            cpa16(&Bs[nxt][lr_][lc],      Bt + (size_t)(col0 + lr_)*K + k0 + lc);
            cpa16(&Bs[nxt][lr_ + 64][lc], Bt + (size_t)(col0 + lr_ + 64)*K + k0 + lc);
            asm volatile("cp.async.commit_group;");
            asm volatile("cp.async.wait_group 1;");
        } else {
            asm volatile("cp.async.wait_group 0;");
        }
        __syncthreads();
        #pragma unroll
        for (int ks = 0; ks < 2; ks++){
            unsigned af[4][4], bfrg[4][2];
            #pragma unroll
            for (int mt = 0; mt < 4; mt++){
                int rm = wm + mt*16;
                af[mt][0] = *(unsigned*)&As[cur][rm + g    ][ks*16 + tg*2];
                af[mt][1] = *(unsigned*)&As[cur][rm + g + 8][ks*16 + tg*2];
                af[mt][2] = *(unsigned*)&As[cur][rm + g    ][ks*16 + tg*2 + 8];
                af[mt][3] = *(unsigned*)&As[cur][rm + g + 8][ks*16 + tg*2 + 8];
            }
            #pragma unroll
            for (int nt = 0; nt < 4; nt++){
                int rn = wn + nt*8 + g;
                bfrg[nt][0] = *(unsigned*)&Bs[cur][rn][ks*16 + tg*2];
                bfrg[nt][1] = *(unsigned*)&Bs[cur][rn][ks*16 + tg*2 + 8];
            }
            #pragma unroll
            for (int mt = 0; mt < 4; mt++)
                #pragma unroll
                for (int nt = 0; nt < 4; nt++)
                    asm volatile(
                        "mma.sync.aligned.m16n8k16.row.col.f32.bf16.bf16.f32 "
                        "{%0,%1,%2,%3},{%4,%5,%6,%7},{%8,%9},{%0,%1,%2,%3};"
                        : "+f"(acc[mt][nt][0]), "+f"(acc[mt][nt][1]),
                          "+f"(acc[mt][nt][2]), "+f"(acc[mt][nt][3])
                        : "r"(af[mt][0]), "r"(af[mt][1]), "r"(af[mt][2]), "r"(af[mt][3]),
                          "r"(bfrg[nt][0]), "r"(bfrg[nt][1]));
        }
        __syncthreads();
    }
    float p1[4][2] = {}, p2[4][2] = {};
    #pragma unroll
    for (int mt = 0; mt < 4; mt++){
        #pragma unroll
        for (int nt = 0; nt < 4; nt++){
            int col = col0 + wn + nt*8 + tg*2;
            float b0v = 0.f, b1v = 0.f;
            if (bias){ b0v = bias[col]; b1v = bias[col+1]; }
            #pragma unroll
            for (int h = 0; h < 2; h++){
                int row = row0 + wm + mt*16 + g + h*8;
                float v0 = acc[mt][nt][h*2+0] + b0v;
                float v1 = acc[mt][nt][h*2+1] + b1v;
                if (relu){ v0 = fmaxf(v0, 0.f); v1 = fmaxf(v1, 0.f); }
                if (C8){
                    __nv_fp8x2_storage_t e = __nv_cvt_float2_to_fp8x2(
                        make_float2(v0*FSC, v1*FSC), __NV_SATFINITE, __NV_E4M3);
                    *(unsigned short*)(C8 + (size_t)row*N + col) = (unsigned short)e;
                    if (atta){
                        __half2_raw hr = __nv_cvt_fp8x2_to_halfraw2(e, __NV_E4M3);
                        float2 d = __half22float2(*(__half2*)&hr);
                        p1[mt][h] += d.x*atta[col]     + d.y*atta[col+1];
                        p2[mt][h] += d.x*atta[DIM+col] + d.y*atta[DIM+col+1];
                    }
                } else if (Cb){
                    *(__nv_bfloat162*)(Cb + (size_t)row*N + col) =
                        __floats2bfloat162_rn(v0, v1);
                }
                if (W3) p1[mt][h] += v0*W3[col] + v1*W3[col+1];
            }
        }
    }
    if (atta || W3){
        #pragma unroll
        for (int mt = 0; mt < 4; mt++){
            #pragma unroll
            for (int h = 0; h < 2; h++){
                int row = row0 + wm + mt*16 + g + h*8;
                float a = p1[mt][h];
                a += __shfl_xor_sync(0xffffffffu, a, 1);
                a += __shfl_xor_sync(0xffffffffu, a, 2);
                if (atta){
                    float b = p2[mt][h];
                    b += __shfl_xor_sync(0xffffffffu, b, 1);
                    b += __shfl_xor_sync(0xffffffffu, b, 2);
                    if (tg == 0 && row < rowlim){
                        atomicAdd(&al[row], a*FSCI);   // logits in TRUE units
                        atomicAdd(&ar[row], b*FSCI);
                    }
                } else if (tg == 0){
                    atomicAdd(&sv[row], a);
                }
            }
        }
    }
}

// ---------------- fused CSR attention, both graphs (z-batched), fp8 --------
__global__ void att_csr2_k(const int* __restrict__ off0, const int* __restrict__ off1,
                           const int* __restrict__ payg, const int* __restrict__ payd,
                           const float* __restrict__ alg, const float* __restrict__ arg,
                           const float* __restrict__ ald, const float* __restrict__ ard,
                           const unsigned char* __restrict__ hg,
                           const unsigned char* __restrict__ hd,
                           const float* __restrict__ Eg0, const float* __restrict__ Ed0,
                           unsigned char* __restrict__ outg,
                           unsigned char* __restrict__ outd, int n){
    const int* off; const int* pay; const float* al; const float* ar;
    const unsigned char* h; const float* base; unsigned char* out;
    if (blockIdx.z == 0){ off = off0; pay = payg; al = alg; ar = arg; h = hg; base = Eg0; out = outg; }
    else                { off = off1; pay = payd; al = ald; ar = ard; h = hd; base = Ed0; out = outd; }
    int t = (blockIdx.x*blockDim.x + threadIdx.x) >> 5;
    int lane = threadIdx.x & 31;
    if (t >= n) return;
    int s0 = off[t], s1 = off[t+1];
    float art = ar[t];
    float m = -1e30f;
    for (int i = s0 + lane; i < s1; i += 32){
        float x = al[pay[i]] + art;
        x = x > 0.f ? x : 0.2f*x;
        m = fmaxf(m, x);
    }
    #pragma unroll
    for (int o = 16; o; o >>= 1) m = fmaxf(m, __shfl_xor_sync(0xffffffffu, m, o));
    float den = 0.f;
    float acc[8] = {};
    const uint2* hb = (const uint2*)h;
    for (int i = s0; i < s1; i++){
        int s = pay[i];
        float x = al[s] + art;
        x = x > 0.f ? x : 0.2f*x;
        float ex = __expf(x - m);
        den += ex;
        uint2 hv = hb[(size_t)s*32 + lane];
        float f[8]; unpack8_fp8(hv, f);
        #pragma unroll
        for (int j = 0; j < 8; j++) acc[j] += ex*f[j];
    }
    float dinv = 0.1f / (den + 1e-9f);
    const float4* bp = (const float4*)base + (size_t)t*64 + lane*2;
    float4 b0 = bp[0], b1 = bp[1];
    float o[8];
    o[0]=fmaf(acc[0],dinv,FSC*b0.x); o[1]=fmaf(acc[1],dinv,FSC*b0.y);
    o[2]=fmaf(acc[2],dinv,FSC*b0.z); o[3]=fmaf(acc[3],dinv,FSC*b0.w);
    o[4]=fmaf(acc[4],dinv,FSC*b1.x); o[5]=fmaf(acc[5],dinv,FSC*b1.y);
    o[6]=fmaf(acc[6],dinv,FSC*b1.z); o[7]=fmaf(acc[7],dinv,FSC*b1.w);
    ((uint2*)out)[(size_t)t*32 + lane] = pack8_fp8(o);
}

// ---------------- CSR SpMM (fp8 src) directly into MLP input rows ----------
__global__ void spmm_cat_k(const int* __restrict__ off2, const int2* __restrict__ pe1,
                           const int* __restrict__ off3, const int2* __restrict__ pe2,
                           const unsigned char* __restrict__ Eg0b,
                           const unsigned char* __restrict__ Ed0b,
                           const int* __restrict__ uids, const int* __restrict__ pos,
                           const int* __restrict__ neg,
                           __nv_bfloat16* __restrict__ catb){
    int w = (blockIdx.x*blockDim.x + threadIdx.x) >> 5;
    int lane = threadIdx.x & 31;
    if (w >= 3*B_) return;
    const int* off; const int2* pe; const uint2* src;
    int r; uint4* dst0; uint4* dst1 = nullptr;
    uint4* cb = (uint4*)catb;
    if (w < B_){
        r = uids[w]; off = off2; pe = pe1; src = (const uint2*)Ed0b;
        dst0 = cb + (size_t)w*64 + lane;
        dst1 = cb + (size_t)(w + B_)*64 + lane;
    } else if (w < 2*B_){
        int b = w - B_;
        r = pos[b]; off = off3; pe = pe2; src = (const uint2*)Eg0b;
        dst0 = cb + (size_t)b*64 + 32 + lane;
    } else {
        int b = w - 2*B_;
        r = neg[b]; off = off3; pe = pe2; src = (const uint2*)Eg0b;
        dst0 = cb + (size_t)(b + B_)*64 + 32 + lane;
    }
    int s0 = off[r], s1 = off[r+1];
    float acc[8] = {};
    for (int i = s0; i < s1; i++){
        int2 e = pe[i];
        float v = __int_as_float(e.y);
        if (v == 0.f) continue;
        uint2 sv = src[(size_t)e.x*32 + lane];
        float f[8]; unpack8_fp8(sv, f);
        #pragma unroll
        for (int j = 0; j < 8; j++) acc[j] += v*f[j];
    }
    float ou[8];
    #pragma unroll
    for (int j = 0; j < 8; j++) ou[j] = acc[j]*FSCI;
    uint4 o = pack8(ou);
    *dst0 = o;
    if (dst1) *dst1 = o;
}

// ---------------- loss_r reduction (adds b3 to scores) ---------------------
__global__ void loss_k(const float* __restrict__ s, const float* __restrict__ b3,
                       int B, double* acc){
    __shared__ double sh[256];
    float b3v = b3[0];
    double local = 0.0;
    for (int i = blockIdx.x*blockDim.x + threadIdx.x; i < B; i += gridDim.x*blockDim.x){
        double ps = s[i] + b3v, ns = s[B + i] + b3v;
        local += softplusd(-ps) + softplusd(ns) + softplusd(ns - ps);
    }
    sh[threadIdx.x] = local;
    __syncthreads();
    for (int st = 128; st; st >>= 1){
        if (threadIdx.x < st) sh[threadIdx.x] += sh[threadIdx.x + st];
        __syncthreads();
    }
    if (threadIdx.x == 0) atomicAdd(acc, sh[0]);
}

// ---------------- sum of squares over all 16 params, one launch ------------
__global__ void sumsq16_k(P16 a, double* acc){
    const float* p = a.p[blockIdx.y];
    int n = a.n[blockIdx.y];
    __shared__ double sh[256];
    double local = 0.0;
    for (int i = blockIdx.x*blockDim.x + threadIdx.x; i < n; i += gridDim.x*blockDim.x){
        double v = p[i];
        local += v*v;
    }
    sh[threadIdx.x] = local;
    __syncthreads();
    for (int st = 128; st; st >>= 1){
        if (threadIdx.x < st) sh[threadIdx.x] += sh[threadIdx.x + st];
        __syncthreads();
    }
    if (threadIdx.x == 0 && sh[0] != 0.0) atomicAdd(acc, sh[0]);
}

// ---------------- final combine --------------------------------------------
__global__ void final_k(const double* lr, const double* reg, float* out, int B){
    double l_r = (*lr) / (double)B;
    out[0] = (float)(1e-7 * (*reg) + l_r);
    out[1] = (float)l_r;
    out[2] = 0.f;
}

// ---------------- launch ----------------------------------------------------
extern "C" void kernel_launch(void* const* d_in, const int* in_sizes, int n_in,
                              void* d_out, int out_size){
    const float* Eg0  = (const float*)d_in[0];
    const float* Ed0  = (const float*)d_in[1];
    const float* attW = (const float*)d_in[2];
    const float* atta = (const float*)d_in[3];
    const float* W1   = (const float*)d_in[6];
    const float* b1   = (const float*)d_in[7];
    const float* W2   = (const float*)d_in[8];
    const float* b2   = (const float*)d_in[9];
    const float* W3   = (const float*)d_in[10];
    const float* b3   = (const float*)d_in[11];
    const float* adj_vals = (const float*)d_in[16];
    const int* uids = (const int*)d_in[17];
    const int* pos  = (const int*)d_in[19];
    const int* neg  = (const int*)d_in[20];
    const int* ge   = (const int*)d_in[21];
    const int* de   = (const int*)d_in[22];
    const int* arows = (const int*)d_in[23];
    const int* acols = (const int*)d_in[24];
    const unsigned* drop1 = (const unsigned*)d_in[25];
    const unsigned* drop2 = (const unsigned*)d_in[26];
    float* out = (float*)d_out;

    float *alg,*arg,*ald,*ard,*sv;
    int *ctl,*offs,*payg,*payd;
    int2 *pe1,*pe2;
    unsigned char *hg8,*hd8,*Eg0b8,*Ed0b8;
    __nv_bfloat16 *Eg0h,*Ed0h,*attWt,*W1t,*W2t,*catb,*h1b;
    double *lr,*reg;
    cudaGetSymbolAddress((void**)&alg,  d_alg);
    cudaGetSymbolAddress((void**)&arg,  d_arg_);
    cudaGetSymbolAddress((void**)&ald,  d_ald);
    cudaGetSymbolAddress((void**)&ard,  d_ard);
    cudaGetSymbolAddress((void**)&sv,   d_s);
    cudaGetSymbolAddress((void**)&ctl,  d_ctl);
    cudaGetSymbolAddress((void**)&offs, d_off);
    cudaGetSymbolAddress((void**)&payg, d_payg);
    cudaGetSymbolAddress((void**)&payd, d_payd);
    cudaGetSymbolAddress((void**)&pe1,  d_pe1);
    cudaGetSymbolAddress((void**)&pe2,  d_pe2);
    cudaGetSymbolAddress((void**)&hg8,  d_hg8);
    cudaGetSymbolAddress((void**)&hd8,  d_hd8);
    cudaGetSymbolAddress((void**)&Eg0b8,d_Eg0b8);
    cudaGetSymbolAddress((void**)&Ed0b8,d_Ed0b8);
    cudaGetSymbolAddress((void**)&Eg0h, d_Eg0h);
    cudaGetSymbolAddress((void**)&Ed0h, d_Ed0h);
    cudaGetSymbolAddress((void**)&attWt,d_attWt);
    cudaGetSymbolAddress((void**)&W1t,  d_W1t);
    cudaGetSymbolAddress((void**)&W2t,  d_W2t);
    cudaGetSymbolAddress((void**)&catb, d_catb);
    cudaGetSymbolAddress((void**)&h1b,  d_h1b);
    cudaGetSymbolAddress((void**)&lr,   d_lr_acc);
    cudaGetSymbolAddress((void**)&reg,  d_reg_acc);

    const int NP1 = NN + 1;
    int* cnt0 = ctl;            int* cnt1 = ctl + NP1;
    int* cur0 = ctl + 2*NP1;    int* cur1 = ctl + 3*NP1;
    int* cnt2 = ctl + 4*NP1;    int* cnt3 = ctl + 5*NP1;
    int* cur2 = ctl + 6*NP1;    int* cur3 = ctl + 7*NP1;
    int* off0 = offs;           int* off1 = offs + NP1;
    int* off2 = offs + 2*NP1;   int* off3 = offs + 3*NP1;

    // fork-join streams (host-side objects only; cost is capture-time only)
    cudaStream_t sB, sC;
    cudaStreamCreateWithFlags(&sB, cudaStreamNonBlocking);
    cudaStreamCreateWithFlags(&sC, cudaStreamNonBlocking);
    cudaEvent_t evRoot, evAtt, evAdj, evW, evC;
    cudaEventCreateWithFlags(&evRoot, cudaEventDisableTiming);
    cudaEventCreateWithFlags(&evAtt,  cudaEventDisableTiming);
    cudaEventCreateWithFlags(&evAdj,  cudaEventDisableTiming);
    cudaEventCreateWithFlags(&evW,    cudaEventDisableTiming);
    cudaEventCreateWithFlags(&evC,    cudaEventDisableTiming);

    cudaEventRecord(evRoot, 0);
    cudaStreamWaitEvent(sB, evRoot, 0);
    cudaStreamWaitEvent(sC, evRoot, 0);

    // ---- stream B: CSR build chain (evAtt mid-chain for free) ----
    cudaMemsetAsync(ctl, 0, sizeof(int)*8*NP1, sB);
    hist4_k<<<(2*NE_+2*NNZ_+255)/256, 256, 0, sB>>>(ge+NE_, de+NE_, arows, acols,
                                                    cnt0, cnt1, cnt2, cnt3);
    ScanArgs sa;
    sa.cnt[0]=cnt0; sa.cnt[1]=cnt1; sa.cnt[2]=cnt2; sa.cnt[3]=cnt3;
    sa.off[0]=off0; sa.off[1]=off1; sa.off[2]=off2; sa.off[3]=off3;
    scan4_k<<<4, 256, 0, sB>>>(sa, NN);
    build_att2_k<<<dim3((NE_+255)/256, 1, 2), 256, 0, sB>>>(ge, de, cur0, cur1,
                                                            off0, off1, payg, payd);
    cudaEventRecord(evAtt, sB);
    build_adj2_k<<<dim3((NNZ_+255)/256, 1, 2), 256, 0, sB>>>(arows, acols, adj_vals,
        drop1, drop2, cur2, cur3, off2, off3, pe1, pe2);
    cudaEventRecord(evAdj, sB);

    // ---- stream C: zeroing + weight transposes (evW), then regularizer (evC)
    cudaMemsetAsync(lr,  0, sizeof(double), sC);
    cudaMemsetAsync(reg, 0, sizeof(double), sC);
    cudaMemsetAsync(sv,  0, sizeof(float)*2*B_, sC);
    cudaMemsetAsync(alg, 0, sizeof(float)*NN, sC);
    cudaMemsetAsync(arg, 0, sizeof(float)*NN, sC);
    cudaMemsetAsync(ald, 0, sizeof(float)*NN, sC);
    cudaMemsetAsync(ard, 0, sizeof(float)*NN, sC);
    convT3_k<<<dim3((2*DIM*DIM+255)/256, 1, 3), 256, 0, sC>>>(attW, W1, W2,
                                                              attWt, W1t, W2t);
    cudaEventRecord(evW, sC);
    P16 pp;
    for (int i = 0; i < 16; i++){ pp.p[i] = (const float*)d_in[i]; pp.n[i] = in_sizes[i]; }
    sumsq16_k<<<dim3(48, 16), 256, 0, sC>>>(pp, reg);
    cudaEventRecord(evC, sC);

    // ---- main stream: conv -> GEMM(+rowdot, fp8 out) -> att -> spmm -> MLP ----
    conv2_k<<<(2*NN*DIM/4+255)/256, 256>>>(Eg0, Ed0, Eg0h, Ed0h, NN*DIM/4);
    cudaStreamWaitEvent(0, evW, 0);
    hgemm_k<<<dim3(DIM/128, NNP/128, 2), 256>>>(NNP, DIM, DIM,
        Eg0h, Ed0h, attWt, hg8, hd8, nullptr, nullptr, nullptr, 0,
        atta, alg, arg, ald, ard, NN, nullptr, nullptr);

    // join att CSR; single z-batched attention launch
    cudaStreamWaitEvent(0, evAtt, 0);
    att_csr2_k<<<dim3((NN*32+255)/256, 1, 2), 256>>>(off0, off1, payg, payd,
        alg, arg, ald, ard, hg8, hd8, Eg0, Ed0, Eg0b8, Ed0b8, NN);

    // SpMM straight into MLP input rows (uids/pos/neg only); needs adj CSR
    cudaStreamWaitEvent(0, evAdj, 0);
    spmm_cat_k<<<(3*B_*32+255)/256, 256>>>(off2, pe1, off3, pe2,
                                           Eg0b8, Ed0b8, uids, pos, neg, catb);

    // MLP: layer1 -> bf16 h1; layer2 fused with score atomics (no h2 buffer)
    hgemm_k<<<dim3(DIM/128, (2*B_)/128, 1), 256>>>(2*B_, DIM, 2*DIM,
        catb, catb, W1t, nullptr, nullptr, h1b, h1b, b1, 1,
        nullptr, nullptr, nullptr, nullptr, nullptr, 0, nullptr, nullptr);
    hgemm_k<<<dim3(DIM/128, (2*B_)/128, 1), 256>>>(2*B_, DIM, DIM,
        h1b, h1b, W2t, nullptr, nullptr, nullptr, nullptr, b2, 1,
        nullptr, nullptr, nullptr, nullptr, nullptr, 0, W3, sv);

    loss_k<<<64, 256>>>(sv, b3, B_, lr);
    cudaStreamWaitEvent(0, evC, 0);
    final_k<<<1, 1>>>(lr, reg, out, B_);

    cudaEventDestroy(evRoot); cudaEventDestroy(evAtt); cudaEventDestroy(evAdj);
    cudaEventDestroy(evW); cudaEventDestroy(evC);
    cudaStreamDestroy(sB); cudaStreamDestroy(sC);
}

// round 17
// speedup vs baseline: 1.1412x; 1.1412x over previous
#include <cuda_runtime.h>
#include <cuda_bf16.h>
#include <cuda_fp16.h>
#include <cuda_fp8.h>
#include <math.h>

#define NN    20000     // N_U == N_I
#define NNP   20096     // padded to multiple of 128
#define DIM   256
#define NNZ_  600000
#define NE_   300000
#define B_    8192
#define FSC   512.0f    // fp8 storage scale
#define FSCI  (1.0f/512.0f)

// ---------------- persistent device scratch (no allocations allowed) -------
__device__ float d_alg[NN], d_arg_[NN], d_ald[NN], d_ard[NN];
__device__ float d_s[2*B_];
__device__ double d_lr_acc, d_reg_acc;
// CSR structures (rebuilt every launch)
__device__ int   d_ctl[8*(NN+1)];            // cnt0,cnt1,cur0,cur1,cnt2,cnt3,cur2,cur3
__device__ int   d_off[4*(NN+1)];            // off0, off1, off2, off3
__device__ int   d_payg[NE_], d_payd[NE_];   // attention payload: src node
__device__ int2  d_pe1[NNZ_], d_pe2[NNZ_];   // spmm payload: {col, w-bits}
// fp8 scratch (values stored scaled by FSC)
__device__ unsigned char d_hg8[NNP*DIM], d_hd8[NNP*DIM];     // h = X @ att_W
__device__ unsigned char d_Eg0b8[NN*DIM], d_Ed0b8[NN*DIM];   // post-attention emb
// bf16 scratch
__device__ __nv_bfloat16 d_Eg0h[NNP*DIM], d_Ed0h[NNP*DIM];   // padded rows stay 0
__device__ __nv_bfloat16 d_attWt[DIM*DIM];                    // [N,K] transposed
__device__ __nv_bfloat16 d_W1t[DIM*2*DIM], d_W2t[DIM*DIM];    // transposed
__device__ __nv_bfloat16 d_catb[2*B_*2*DIM], d_h1b[2*B_*DIM];

struct ScanArgs { const int* cnt[4]; int* off[4]; };
struct P16 { const float* p[16]; int n[16]; };

__device__ __forceinline__ double softplusd(double x){
    return fmax(x, 0.0) + log1p(exp(-fabs(x)));
}

__device__ __forceinline__ uint4 pack8(const float* f){
    uint4 v;
    __nv_bfloat162* p = (__nv_bfloat162*)&v;
    #pragma unroll
    for (int i = 0; i < 4; i++)
        p[i] = __floats2bfloat162_rn(f[2*i], f[2*i+1]);
    return v;
}

// 8 e4m3 bytes (uint2) -> 8 floats (still in FSC-scaled units)
__device__ __forceinline__ void unpack8_fp8(uint2 v, float* f){
    __nv_fp8x2_storage_t* p = (__nv_fp8x2_storage_t*)&v;
    #pragma unroll
    for (int i = 0; i < 4; i++){
        __half2_raw hr = __nv_cvt_fp8x2_to_halfraw2(p[i], __NV_E4M3);
        float2 t = __half22float2(*(__half2*)&hr);
        f[2*i] = t.x; f[2*i+1] = t.y;
    }
}

// 8 floats (FSC-scaled) -> 8 e4m3 bytes
__device__ __forceinline__ uint2 pack8_fp8(const float* f){
    uint2 v;
    __nv_fp8x2_storage_t* p = (__nv_fp8x2_storage_t*)&v;
    #pragma unroll
    for (int i = 0; i < 4; i++)
        p[i] = __nv_cvt_float2_to_fp8x2(make_float2(f[2*i], f[2*i+1]),
                                        __NV_SATFINITE, __NV_E4M3);
    return v;
}

// ---------------- f32 -> bf16, both embedding tables, vectorized ----------
__global__ void conv2_k(const float* __restrict__ a, const float* __restrict__ b,
                        __nv_bfloat16* __restrict__ oa, __nv_bfloat16* __restrict__ ob,
                        int nvec){
    int i = blockIdx.x*blockDim.x + threadIdx.x;
    if (i >= 2*nvec) return;
    const float* src; __nv_bfloat16* dst; int j;
    if (i < nvec){ src = a; dst = oa; j = i; }
    else         { src = b; dst = ob; j = i - nvec; }
    float4 v = ((const float4*)src)[j];
    __nv_bfloat162 lo = __floats2bfloat162_rn(v.x, v.y);
    __nv_bfloat162 hi = __floats2bfloat162_rn(v.z, v.w);
    uint2 pk; pk.x = *(unsigned*)&lo; pk.y = *(unsigned*)&hi;
    ((uint2*)dst)[j] = pk;
}

// ---------------- all three weight transposes, one launch ------------------
__global__ void convT3_k(const float* __restrict__ attW, const float* __restrict__ W1,
                         const float* __restrict__ W2,
                         __nv_bfloat16* __restrict__ attWt, __nv_bfloat16* __restrict__ W1t,
                         __nv_bfloat16* __restrict__ W2t){
    int z = blockIdx.z;
    const float* in; __nv_bfloat16* out; int K, N;
    if (z == 0){ in = attW; out = attWt; K = DIM;   N = DIM; }
    else if (z == 1){ in = W1; out = W1t; K = 2*DIM; N = DIM; }
    else { in = W2; out = W2t; K = DIM; N = DIM; }
    int i = blockIdx.x*blockDim.x + threadIdx.x;
    if (i >= K*N) return;
    int k = i / N, n = i % N;
    out[(size_t)n*K + k] = __float2bfloat16(in[i]);
}

// ---------------- all four histograms, one launch --------------------------
__global__ void hist4_k(const int* __restrict__ k0, const int* __restrict__ k1,
                        const int* __restrict__ k2, const int* __restrict__ k3,
                        int* __restrict__ c0, int* __restrict__ c1,
                        int* __restrict__ c2, int* __restrict__ c3){
    int i = blockIdx.x*blockDim.x + threadIdx.x;
    if (i < NE_)                  atomicAdd(&c0[k0[i]], 1);
    else if (i < 2*NE_)           atomicAdd(&c1[k1[i - NE_]], 1);
    else if (i < 2*NE_ + NNZ_)    atomicAdd(&c2[k2[i - 2*NE_]], 1);
    else if (i < 2*NE_ + 2*NNZ_)  atomicAdd(&c3[k3[i - 2*NE_ - NNZ_]], 1);
}

// one block per array; 256 threads; exclusive scan of n counts -> off[0..n]
__global__ void scan4_k(ScanArgs a, int n){
    const int* cnt = a.cnt[blockIdx.x];
    int* off = a.off[blockIdx.x];
    __shared__ int part[256];
    int tid = threadIdx.x;
    int per = (n + 255) / 256;
    int st = tid*per, en = st + per; if (en > n) en = n;
    int s = 0;
    for (int i = st; i < en; i++) s += cnt[i];
    part[tid] = s;
    __syncthreads();
    for (int o = 1; o < 256; o <<= 1){
        int v = (tid >= o) ? part[tid - o] : 0;
        __syncthreads();
        part[tid] += v;
        __syncthreads();
    }
    int base = tid ? part[tid - 1] : 0;
    for (int i = st; i < en; i++){ off[i] = base; base += cnt[i]; }
    if (tid == 255) off[n] = part[255];
}

// ---------------- attention CSR build, both graphs (z-batched) -------------
__global__ void build_att2_k(const int* __restrict__ ge, const int* __restrict__ de,
                             int* __restrict__ cur0, int* __restrict__ cur1,
                             const int* __restrict__ off0, const int* __restrict__ off1,
                             int* __restrict__ payg, int* __restrict__ payd){
    int i = blockIdx.x*blockDim.x + threadIdx.x;
    if (i >= NE_) return;
    const int* src; const int* tgt; int* cur; const int* off; int* pay;
    if (blockIdx.z == 0){ src = ge; tgt = ge + NE_; cur = cur0; off = off0; pay = payg; }
    else                { src = de; tgt = de + NE_; cur = cur1; off = off1; pay = payd; }
    int t = tgt[i];
    int p = atomicAdd(&cur[t], 1);
    pay[off[t] + p] = src[i];
}

// ---------------- adjacency CSR build + dropout weights, packed int2 -------
__global__ void build_adj2_k(const int* __restrict__ arows, const int* __restrict__ acols,
                             const float* __restrict__ vals,
                             const unsigned* __restrict__ m1, const unsigned* __restrict__ m2,
                             int* __restrict__ cur2, int* __restrict__ cur3,
                             const int* __restrict__ off2, const int* __restrict__ off3,
                             int2* __restrict__ pe1, int2* __restrict__ pe2){
    int i = blockIdx.x*blockDim.x + threadIdx.x;
    if (i >= NNZ_) return;
    const int* keys; const int* other; const unsigned* mask;
    int* cur; const int* off; int2* pe;
    if (blockIdx.z == 0){ keys = arows; other = acols; mask = m1; cur = cur2; off = off2; pe = pe1; }
    else                { keys = acols; other = arows; mask = m2; cur = cur3; off = off3; pe = pe2; }
    int k = keys[i];
    int p = atomicAdd(&cur[k], 1);
    float w = mask[i] ? vals[i] * (1.0f/0.9f) : 0.f;
    pe[off[k] + p] = make_int2(other[i], __float_as_int(w));
}

// ---------------- bf16 tensor-core GEMM with fused epilogues (R14) ---------
// C[M,N] = A[M,K] @ B[K,N]; A bf16 row-major, Bt = B^T bf16 [N,K].
// Outputs: fp8 store scaled by FSC (C8*), or bf16 store (Cb*).
// Optional: attention rowdot atomics from fp8-rounded values (atta/al/ar),
// final-score atomics (W3/sv). blockIdx.z selects batch.
__global__ void hgemm_k(int M, int N, int K,
    const __nv_bfloat16* __restrict__ A0, const __nv_bfloat16* __restrict__ A1,
    const __nv_bfloat16* __restrict__ Bt,
    unsigned char* __restrict__ C80, unsigned char* __restrict__ C81,
    __nv_bfloat16* __restrict__ Cb0, __nv_bfloat16* __restrict__ Cb1,
    const float* __restrict__ bias, int relu,
    const float* __restrict__ atta,
    float* __restrict__ al0, float* __restrict__ ar0,
    float* __restrict__ al1, float* __restrict__ ar1, int rowlim,
    const float* __restrict__ W3, float* __restrict__ sv){
    const __nv_bfloat16* A = blockIdx.z ? A1 : A0;
    unsigned char* C8 = blockIdx.z ? C81 : C80;
    __nv_bfloat16* Cb = blockIdx.z ? Cb1 : Cb0;
    float* al = blockIdx.z ? al1 : al0;
    float* ar = blockIdx.z ? ar1 : ar0;
    __shared__ __nv_bfloat16 As[128][40];
    __shared__ __nv_bfloat16 Bs[128][40];
    int tid = threadIdx.x;
    int wid = tid >> 5, lane = tid & 31;
    int g = lane >> 2, tg = lane & 3;
    int wm = (wid & 1) * 64, wn = (wid >> 1) * 32;
    int row0 = blockIdx.y * 128, col0 = blockIdx.x * 128;
    float acc[4][4][4] = {};
    for (int k0 = 0; k0 < K; k0 += 32){
        #pragma unroll
        for (int i = 0; i < 2; i++){
            int idx = tid + i*256;
            int r = idx >> 2, c = (idx & 3) * 8;
            *(uint4*)&As[r][c] = *(const uint4*)(A  + (size_t)(row0 + r)*K + k0 + c);
            *(uint4*)&Bs[r][c] = *(const uint4*)(Bt + (size_t)(col0 + r)*K + k0 + c);
        }
        __syncthreads();
        #pragma unroll
        for (int ks = 0; ks < 2; ks++){
            unsigned af[4][4], bfrg[4][2];
            #pragma unroll
            for (int mt = 0; mt < 4; mt++){
                int rm = wm + mt*16;
                af[mt][0] = *(unsigned*)&As[rm + g    ][ks*16 + tg*2];
                af[mt][1] = *(unsigned*)&As[rm + g + 8][ks*16 + tg*2];
                af[mt][2] = *(unsigned*)&As[rm + g    ][ks*16 + tg*2 + 8];
                af[mt][3] = *(unsigned*)&As[rm + g + 8][ks*16 + tg*2 + 8];
            }
            #pragma unroll
            for (int nt = 0; nt < 4; nt++){
                int rn = wn + nt*8 + g;
                bfrg[nt][0] = *(unsigned*)&Bs[rn][ks*16 + tg*2];
                bfrg[nt][1] = *(unsigned*)&Bs[rn][ks*16 + tg*2 + 8];
            }
            #pragma unroll
            for (int mt = 0; mt < 4; mt++)
                #pragma unroll
                for (int nt = 0; nt < 4; nt++)
                    asm volatile(
                        "mma.sync.aligned.m16n8k16.row.col.f32.bf16.bf16.f32 "
                        "{%0,%1,%2,%3},{%4,%5,%6,%7},{%8,%9},{%0,%1,%2,%3};"
                        : "+f"(acc[mt][nt][0]), "+f"(acc[mt][nt][1]),
                          "+f"(acc[mt][nt][2]), "+f"(acc[mt][nt][3])
                        : "r"(af[mt][0]), "r"(af[mt][1]), "r"(af[mt][2]), "r"(af[mt][3]),
                          "r"(bfrg[nt][0]), "r"(bfrg[nt][1]));
        }
        __syncthreads();
    }
    float p1[4][2] = {}, p2[4][2] = {};
    #pragma unroll
    for (int mt = 0; mt < 4; mt++){
        #pragma unroll
        for (int nt = 0; nt < 4; nt++){
            int col = col0 + wn + nt*8 + tg*2;
            float b0v = 0.f, b1v = 0.f;
            if (bias){ b0v = bias[col]; b1v = bias[col+1]; }
            #pragma unroll
            for (int h = 0; h < 2; h++){
                int row = row0 + wm + mt*16 + g + h*8;
                float v0 = acc[mt][nt][h*2+0] + b0v;
                float v1 = acc[mt][nt][h*2+1] + b1v;
                if (relu){ v0 = fmaxf(v0, 0.f); v1 = fmaxf(v1, 0.f); }
                if (C8){
                    __nv_fp8x2_storage_t e = __nv_cvt_float2_to_fp8x2(
                        make_float2(v0*FSC, v1*FSC), __NV_SATFINITE, __NV_E4M3);
                    *(unsigned short*)(C8 + (size_t)row*N + col) = (unsigned short)e;
                    if (atta){
                        __half2_raw hr = __nv_cvt_fp8x2_to_halfraw2(e, __NV_E4M3);
                        float2 d = __half22float2(*(__half2*)&hr);
                        p1[mt][h] += d.x*atta[col]     + d.y*atta[col+1];
                        p2[mt][h] += d.x*atta[DIM+col] + d.y*atta[DIM+col+1];
                    }
                } else if (Cb){
                    *(__nv_bfloat162*)(Cb + (size_t)row*N + col) =
                        __floats2bfloat162_rn(v0, v1);
                }
                if (W3) p1[mt][h] += v0*W3[col] + v1*W3[col+1];
            }
        }
    }
    if (atta || W3){
        #pragma unroll
        for (int mt = 0; mt < 4; mt++){
            #pragma unroll
            for (int h = 0; h < 2; h++){
                int row = row0 + wm + mt*16 + g + h*8;
                float a = p1[mt][h];
                a += __shfl_xor_sync(0xffffffffu, a, 1);
                a += __shfl_xor_sync(0xffffffffu, a, 2);
                if (atta){
                    float b = p2[mt][h];
                    b += __shfl_xor_sync(0xffffffffu, b, 1);
                    b += __shfl_xor_sync(0xffffffffu, b, 2);
                    if (tg == 0 && row < rowlim){
                        atomicAdd(&al[row], a*FSCI);   // logits in TRUE units
                        atomicAdd(&ar[row], b*FSCI);
                    }
                } else if (tg == 0){
                    atomicAdd(&sv[row], a);
                }
            }
        }
    }
}

// ---------------- fused CSR attention, both graphs (z-batched), fp8 --------
// Edge loop unrolled 2-wide: both gathers in flight before either accumulate.
__global__ void att_csr2_k(const int* __restrict__ off0, const int* __restrict__ off1,
                           const int* __restrict__ payg, const int* __restrict__ payd,
                           const float* __restrict__ alg, const float* __restrict__ arg,
                           const float* __restrict__ ald, const float* __restrict__ ard,
                           const unsigned char* __restrict__ hg,
                           const unsigned char* __restrict__ hd,
                           const float* __restrict__ Eg0, const float* __restrict__ Ed0,
                           unsigned char* __restrict__ outg,
                           unsigned char* __restrict__ outd, int n){
    const int* off; const int* pay; const float* al; const float* ar;
    const unsigned char* h; const float* base; unsigned char* out;
    if (blockIdx.z == 0){ off = off0; pay = payg; al = alg; ar = arg; h = hg; base = Eg0; out = outg; }
    else                { off = off1; pay = payd; al = ald; ar = ard; h = hd; base = Ed0; out = outd; }
    int t = (blockIdx.x*blockDim.x + threadIdx.x) >> 5;
    int lane = threadIdx.x & 31;
    if (t >= n) return;
    int s0 = off[t], s1 = off[t+1];
    float art = ar[t];
    float m = -1e30f;
    for (int i = s0 + lane; i < s1; i += 32){
        float x = al[pay[i]] + art;
        x = x > 0.f ? x : 0.2f*x;
        m = fmaxf(m, x);
    }
    #pragma unroll
    for (int o = 16; o; o >>= 1) m = fmaxf(m, __shfl_xor_sync(0xffffffffu, m, o));
    float den = 0.f;
    float acc[8] = {};
    const uint2* hb = (const uint2*)h;
    int i = s0;
    for (; i + 1 < s1; i += 2){
        int sA = pay[i], sB = pay[i+1];
        float xA = al[sA] + art, xB = al[sB] + art;
        uint2 hvA = hb[(size_t)sA*32 + lane];
        uint2 hvB = hb[(size_t)sB*32 + lane];
        xA = xA > 0.f ? xA : 0.2f*xA;
        xB = xB > 0.f ? xB : 0.2f*xB;
        float exA = __expf(xA - m), exB = __expf(xB - m);
        den += exA; den += exB;
        float fA[8], fB[8];
        unpack8_fp8(hvA, fA);
        unpack8_fp8(hvB, fB);
        #pragma unroll
        for (int j = 0; j < 8; j++){ acc[j] += exA*fA[j]; acc[j] += exB*fB[j]; }
    }
    if (i < s1){
        int s = pay[i];
        float x = al[s] + art;
        x = x > 0.f ? x : 0.2f*x;
        float ex = __expf(x - m);
        den += ex;
        uint2 hv = hb[(size_t)s*32 + lane];
        float f[8]; unpack8_fp8(hv, f);
        #pragma unroll
        for (int j = 0; j < 8; j++) acc[j] += ex*f[j];
    }
    float dinv = 0.1f / (den + 1e-9f);
    const float4* bp = (const float4*)base + (size_t)t*64 + lane*2;
    float4 b0 = bp[0], b1 = bp[1];
    float o[8];
    o[0]=fmaf(acc[0],dinv,FSC*b0.x); o[1]=fmaf(acc[1],dinv,FSC*b0.y);
    o[2]=fmaf(acc[2],dinv,FSC*b0.z); o[3]=fmaf(acc[3],dinv,FSC*b0.w);
    o[4]=fmaf(acc[4],dinv,FSC*b1.x); o[5]=fmaf(acc[5],dinv,FSC*b1.y);
    o[6]=fmaf(acc[6],dinv,FSC*b1.z); o[7]=fmaf(acc[7],dinv,FSC*b1.w);
    ((uint2*)out)[(size_t)t*32 + lane] = pack8_fp8(o);
}

// ---------------- CSR SpMM (fp8 src) directly into MLP input rows ----------
// Edge loop unrolled 2-wide; no zero-skip branch (latency-bound regime).
__global__ void spmm_cat_k(const int* __restrict__ off2, const int2* __restrict__ pe1,
                           const int* __restrict__ off3, const int2* __restrict__ pe2,
                           const unsigned char* __restrict__ Eg0b,
                           const unsigned char* __restrict__ Ed0b,
                           const int* __restrict__ uids, const int* __restrict__ pos,
                           const int* __restrict__ neg,
                           __nv_bfloat16* __restrict__ catb){
    int w = (blockIdx.x*blockDim.x + threadIdx.x) >> 5;
    int lane = threadIdx.x & 31;
    if (w >= 3*B_) return;
    const int* off; const int2* pe; const uint2* src;
    int r; uint4* dst0; uint4* dst1 = nullptr;
    uint4* cb = (uint4*)catb;
    if (w < B_){
        r = uids[w]; off = off2; pe = pe1; src = (const uint2*)Ed0b;
        dst0 = cb + (size_t)w*64 + lane;
        dst1 = cb + (size_t)(w + B_)*64 + lane;
    } else if (w < 2*B_){
        int b = w - B_;
        r = pos[b]; off = off3; pe = pe2; src = (const uint2*)Eg0b;
        dst0 = cb + (size_t)b*64 + 32 + lane;
    } else {
        int b = w - 2*B_;
        r = neg[b]; off = off3; pe = pe2; src = (const uint2*)Eg0b;
        dst0 = cb + (size_t)(b + B_)*64 + 32 + lane;
    }
    int s0 = off[r], s1 = off[r+1];
    float acc[8] = {};
    int i = s0;
    for (; i + 1 < s1; i += 2){
        int2 eA = pe[i], eB = pe[i+1];
        uint2 svA = src[(size_t)eA.x*32 + lane];
        uint2 svB = src[(size_t)eB.x*32 + lane];
        float vA = __int_as_float(eA.y), vB = __int_as_float(eB.y);
        float fA[8], fB[8];
        unpack8_fp8(svA, fA);
        unpack8_fp8(svB, fB);
        #pragma unroll
        for (int j = 0; j < 8; j++){ acc[j] += vA*fA[j]; acc[j] += vB*fB[j]; }
    }
    if (i < s1){
        int2 e = pe[i];
        float v = __int_as_float(e.y);
        uint2 sv = src[(size_t)e.x*32 + lane];
        float f[8]; unpack8_fp8(sv, f);
        #pragma unroll
        for (int j = 0; j < 8; j++) acc[j] += v*f[j];
    }
    float ou[8];
    #pragma unroll
    for (int j = 0; j < 8; j++) ou[j] = acc[j]*FSCI;
    uint4 o = pack8(ou);
    *dst0 = o;
    if (dst1) *dst1 = o;
}

// ---------------- loss_r reduction (adds b3 to scores) ---------------------
__global__ void loss_k(const float* __restrict__ s, const float* __restrict__ b3,
                       int B, double* acc){
    __shared__ double sh[256];
    float b3v = b3[0];
    double local = 0.0;
    for (int i = blockIdx.x*blockDim.x + threadIdx.x; i < B; i += gridDim.x*blockDim.x){
        double ps = s[i] + b3v, ns = s[B + i] + b3v;
        local += softplusd(-ps) + softplusd(ns) + softplusd(ns - ps);
    }
    sh[threadIdx.x] = local;
    __syncthreads();
    for (int st = 128; st; st >>= 1){
        if (threadIdx.x < st) sh[threadIdx.x] += sh[threadIdx.x + st];
        __syncthreads();
    }
    if (threadIdx.x == 0) atomicAdd(acc, sh[0]);
}

// ---------------- sum of squares over all 16 params, one launch ------------
__global__ void sumsq16_k(P16 a, double* acc){
    const float* p = a.p[blockIdx.y];
    int n = a.n[blockIdx.y];
    __shared__ double sh[256];
    double local = 0.0;
    for (int i = blockIdx.x*blockDim.x + threadIdx.x; i < n; i += gridDim.x*blockDim.x){
        double v = p[i];
        local += v*v;
    }
    sh[threadIdx.x] = local;
    __syncthreads();
    for (int st = 128; st; st >>= 1){
        if (threadIdx.x < st) sh[threadIdx.x] += sh[threadIdx.x + st];
        __syncthreads();
    }
    if (threadIdx.x == 0 && sh[0] != 0.0) atomicAdd(acc, sh[0]);
}

// ---------------- final combine --------------------------------------------
__global__ void final_k(const double* lr, const double* reg, float* out, int B){
    double l_r = (*lr) / (double)B;
    out[0] = (float)(1e-7 * (*reg) + l_r);
    out[1] = (float)l_r;
    out[2] = 0.f;
}

// ---------------- launch ----------------------------------------------------
extern "C" void kernel_launch(void* const* d_in, const int* in_sizes, int n_in,
                              void* d_out, int out_size){
    const float* Eg0  = (const float*)d_in[0];
    const float* Ed0  = (const float*)d_in[1];
    const float* attW = (const float*)d_in[2];
    const float* atta = (const float*)d_in[3];
    const float* W1   = (const float*)d_in[6];
    const float* b1   = (const float*)d_in[7];
    const float* W2   = (const float*)d_in[8];
    const float* b2   = (const float*)d_in[9];
    const float* W3   = (const float*)d_in[10];
    const float* b3   = (const float*)d_in[11];
    const float* adj_vals = (const float*)d_in[16];
    const int* uids = (const int*)d_in[17];
    const int* pos  = (const int*)d_in[19];
    const int* neg  = (const int*)d_in[20];
    const int* ge   = (const int*)d_in[21];
    const int* de   = (const int*)d_in[22];
    const int* arows = (const int*)d_in[23];
    const int* acols = (const int*)d_in[24];
    const unsigned* drop1 = (const unsigned*)d_in[25];
    const unsigned* drop2 = (const unsigned*)d_in[26];
    float* out = (float*)d_out;

    float *alg,*arg,*ald,*ard,*sv;
    int *ctl,*offs,*payg,*payd;
    int2 *pe1,*pe2;
    unsigned char *hg8,*hd8,*Eg0b8,*Ed0b8;
    __nv_bfloat16 *Eg0h,*Ed0h,*attWt,*W1t,*W2t,*catb,*h1b;
    double *lr,*reg;
    cudaGetSymbolAddress((void**)&alg,  d_alg);
    cudaGetSymbolAddress((void**)&arg,  d_arg_);
    cudaGetSymbolAddress((void**)&ald,  d_ald);
    cudaGetSymbolAddress((void**)&ard,  d_ard);
    cudaGetSymbolAddress((void**)&sv,   d_s);
    cudaGetSymbolAddress((void**)&ctl,  d_ctl);
    cudaGetSymbolAddress((void**)&offs, d_off);
    cudaGetSymbolAddress((void**)&payg, d_payg);
    cudaGetSymbolAddress((void**)&payd, d_payd);
    cudaGetSymbolAddress((void**)&pe1,  d_pe1);
    cudaGetSymbolAddress((void**)&pe2,  d_pe2);
    cudaGetSymbolAddress((void**)&hg8,  d_hg8);
    cudaGetSymbolAddress((void**)&hd8,  d_hd8);
    cudaGetSymbolAddress((void**)&Eg0b8,d_Eg0b8);
    cudaGetSymbolAddress((void**)&Ed0b8,d_Ed0b8);
    cudaGetSymbolAddress((void**)&Eg0h, d_Eg0h);
    cudaGetSymbolAddress((void**)&Ed0h, d_Ed0h);
    cudaGetSymbolAddress((void**)&attWt,d_attWt);
    cudaGetSymbolAddress((void**)&W1t,  d_W1t);
    cudaGetSymbolAddress((void**)&W2t,  d_W2t);
    cudaGetSymbolAddress((void**)&catb, d_catb);
    cudaGetSymbolAddress((void**)&h1b,  d_h1b);
    cudaGetSymbolAddress((void**)&lr,   d_lr_acc);
    cudaGetSymbolAddress((void**)&reg,  d_reg_acc);

    const int NP1 = NN + 1;
    int* cnt0 = ctl;            int* cnt1 = ctl + NP1;
    int* cur0 = ctl + 2*NP1;    int* cur1 = ctl + 3*NP1;
    int* cnt2 = ctl + 4*NP1;    int* cnt3 = ctl + 5*NP1;
    int* cur2 = ctl + 6*NP1;    int* cur3 = ctl + 7*NP1;
    int* off0 = offs;           int* off1 = offs + NP1;
    int* off2 = offs + 2*NP1;   int* off3 = offs + 3*NP1;

    // fork-join streams (host-side objects only; cost is capture-time only)
    cudaStream_t sB, sC;
    cudaStreamCreateWithFlags(&sB, cudaStreamNonBlocking);
    cudaStreamCreateWithFlags(&sC, cudaStreamNonBlocking);
    cudaEvent_t evRoot, evAtt, evAdj, evW, evC;
    cudaEventCreateWithFlags(&evRoot, cudaEventDisableTiming);
    cudaEventCreateWithFlags(&evAtt,  cudaEventDisableTiming);
    cudaEventCreateWithFlags(&evAdj,  cudaEventDisableTiming);
    cudaEventCreateWithFlags(&evW,    cudaEventDisableTiming);
    cudaEventCreateWithFlags(&evC,    cudaEventDisableTiming);

    cudaEventRecord(evRoot, 0);
    cudaStreamWaitEvent(sB, evRoot, 0);
    cudaStreamWaitEvent(sC, evRoot, 0);

    // ---- stream B: CSR build chain (evAtt mid-chain for free) ----
    cudaMemsetAsync(ctl, 0, sizeof(int)*8*NP1, sB);
    hist4_k<<<(2*NE_+2*NNZ_+255)/256, 256, 0, sB>>>(ge+NE_, de+NE_, arows, acols,
                                                    cnt0, cnt1, cnt2, cnt3);
    ScanArgs sa;
    sa.cnt[0]=cnt0; sa.cnt[1]=cnt1; sa.cnt[2]=cnt2; sa.cnt[3]=cnt3;
    sa.off[0]=off0; sa.off[1]=off1; sa.off[2]=off2; sa.off[3]=off3;
    scan4_k<<<4, 256, 0, sB>>>(sa, NN);
    build_att2_k<<<dim3((NE_+255)/256, 1, 2), 256, 0, sB>>>(ge, de, cur0, cur1,
                                                            off0, off1, payg, payd);
    cudaEventRecord(evAtt, sB);
    build_adj2_k<<<dim3((NNZ_+255)/256, 1, 2), 256, 0, sB>>>(arows, acols, adj_vals,
        drop1, drop2, cur2, cur3, off2, off3, pe1, pe2);
    cudaEventRecord(evAdj, sB);

    // ---- stream C: zeroing + weight transposes (evW), then regularizer (evC)
    cudaMemsetAsync(lr,  0, sizeof(double), sC);
    cudaMemsetAsync(reg, 0, sizeof(double), sC);
    cudaMemsetAsync(sv,  0, sizeof(float)*2*B_, sC);
    cudaMemsetAsync(alg, 0, sizeof(float)*NN, sC);
    cudaMemsetAsync(arg, 0, sizeof(float)*NN, sC);
    cudaMemsetAsync(ald, 0, sizeof(float)*NN, sC);
    cudaMemsetAsync(ard, 0, sizeof(float)*NN, sC);
    convT3_k<<<dim3((2*DIM*DIM+255)/256, 1, 3), 256, 0, sC>>>(attW, W1, W2,
                                                              attWt, W1t, W2t);
    cudaEventRecord(evW, sC);
    P16 pp;
    for (int i = 0; i < 16; i++){ pp.p[i] = (const float*)d_in[i]; pp.n[i] = in_sizes[i]; }
    sumsq16_k<<<dim3(48, 16), 256, 0, sC>>>(pp, reg);
    cudaEventRecord(evC, sC);

    // ---- main stream: conv -> GEMM(+rowdot, fp8 out) -> att -> spmm -> MLP ----
    conv2_k<<<(2*NN*DIM/4+255)/256, 256>>>(Eg0, Ed0, Eg0h, Ed0h, NN*DIM/4);
    cudaStreamWaitEvent(0, evW, 0);
    hgemm_k<<<dim3(DIM/128, NNP/128, 2), 256>>>(NNP, DIM, DIM,
        Eg0h, Ed0h, attWt, hg8, hd8, nullptr, nullptr, nullptr, 0,
        atta, alg, arg, ald, ard, NN, nullptr, nullptr);

    // join att CSR; single z-batched attention launch
    cudaStreamWaitEvent(0, evAtt, 0);
    att_csr2_k<<<dim3((NN*32+255)/256, 1, 2), 256>>>(off0, off1, payg, payd,
        alg, arg, ald, ard, hg8, hd8, Eg0, Ed0, Eg0b8, Ed0b8, NN);

    // SpMM straight into MLP input rows (uids/pos/neg only); needs adj CSR
    cudaStreamWaitEvent(0, evAdj, 0);
    spmm_cat_k<<<(3*B_*32+255)/256, 256>>>(off2, pe1, off3, pe2,
                                           Eg0b8, Ed0b8, uids, pos, neg, catb);

    // MLP: layer1 -> bf16 h1; layer2 fused with score atomics (no h2 buffer)
    hgemm_k<<<dim3(DIM/128, (2*B_)/128, 1), 256>>>(2*B_, DIM, 2*DIM,
        catb, catb, W1t, nullptr, nullptr, h1b, h1b, b1, 1,
        nullptr, nullptr, nullptr, nullptr, nullptr, 0, nullptr, nullptr);
    hgemm_k<<<dim3(DIM/128, (2*B_)/128, 1), 256>>>(2*B_, DIM, DIM,
        h1b, h1b, W2t, nullptr, nullptr, nullptr, nullptr, b2, 1,
        nullptr, nullptr, nullptr, nullptr, nullptr, 0, W3, sv);

    loss_k<<<64, 256>>>(sv, b3, B_, lr);
    cudaStreamWaitEvent(0, evC, 0);
    final_k<<<1, 1>>>(lr, reg, out, B_);

    cudaEventDestroy(evRoot); cudaEventDestroy(evAtt); cudaEventDestroy(evAdj);
    cudaEventDestroy(evW); cudaEventDestroy(evC);
    cudaStreamDestroy(sB); cudaStreamDestroy(sC);
}